// round 2
// baseline (speedup 1.0000x reference)
#include <cuda_runtime.h>
#include <cstdint>

// Fixed problem geometry: x_list (P=16384, N=1024, 2) float32, scale scalar.
// segn = N/4 = 256 segments per row; segment i uses points 3i..3i+3.
#define N_POINTS   1024
#define SEGN       256

__global__ void __launch_bounds__(SEGN) xing_fused_kernel(
    const float* __restrict__ x,
    const uint32_t* __restrict__ scale_raw,
    float* __restrict__ out, int P)
{
    const int row = blockIdx.x;
    const int t   = threadIdx.x;            // segment index 0..255

    // Row base as float2 (points); segment i starts at point 3i.
    const float2* __restrict__ p =
        reinterpret_cast<const float2*>(x) + (size_t)row * N_POINTS + 3 * t;

    const float2 p0 = __ldg(p + 0);
    const float2 p1 = __ldg(p + 1);
    const float2 p2 = __ldg(p + 2);
    const float2 p3 = __ldg(p + 3);

    const float v1x = p1.x - p0.x, v1y = p1.y - p0.y;
    const float v2x = p2.x - p1.x, v2y = p2.y - p1.y;
    const float v3x = p3.x - p2.x, v3y = p3.y - p2.y;

    // direct = (s12 >= 0) depends only on the sign of cross(v1, v2)
    // (the positive norm product in the denominator cannot flip the sign).
    const float c12 = v1x * v2y - v1y * v2x;
    const float c13 = v1x * v3y - v1y * v3x;

    const float n2   = (v1x * v1x + v1y * v1y) * (v3x * v3x + v3y * v3y);
    const float sina = c13 * rsqrtf(n2);

    // direct -> relu(-sina); else relu(sina)
    float term = (c12 >= 0.0f) ? fmaxf(-sina, 0.0f) : fmaxf(sina, 0.0f);

    // warp reduce
    #pragma unroll
    for (int o = 16; o > 0; o >>= 1)
        term += __shfl_down_sync(0xFFFFFFFFu, term, o);

    __shared__ float s[SEGN / 32];
    if ((t & 31) == 0) s[t >> 5] = term;
    __syncthreads();

    if (t == 0) {
        float v = 0.0f;
        #pragma unroll
        for (int i = 0; i < SEGN / 32; i++) v += s[i];

        // Decode scale: float32 bit pattern vs (small) integer bit pattern.
        uint32_t u = scale_raw[0];
        float f = __uint_as_float(u);
        float scale;
        if (fabsf(f) >= 1e-30f && fabsf(f) < 1e30f) scale = f;        // float32
        else                                        scale = (float)(int)u; // int low word

        atomicAdd(out, v * scale / ((float)SEGN * (float)P));
    }
}

extern "C" void kernel_launch(void* const* d_in, const int* in_sizes, int n_in,
                              void* d_out, int out_size)
{
    const float*    x     = (const float*)d_in[0];
    const uint32_t* scale = (const uint32_t*)d_in[1];
    float*          out   = (float*)d_out;

    // P from element count: in_sizes[0] = P * N_POINTS * 2
    int P = in_sizes[0] / (N_POINTS * 2);

    cudaMemsetAsync(out, 0, sizeof(float));
    xing_fused_kernel<<<P, SEGN>>>(x, scale, out, P);
}

// round 3
// speedup vs baseline: 1.9432x; 1.9432x over previous
#include <cuda_runtime.h>
#include <cstdint>

// Fixed geometry: x_list (P=16384, N=1024, 2) float32, scale scalar.
// segn = N/4 = 256 segments per row; segment i uses points 3i..3i+3.
#define N_POINTS        1024
#define SEGN            256
#define ROWS_PER_BLOCK  8
#define MAX_BLOCKS      4096

__device__ float        g_partials[MAX_BLOCKS];
__device__ unsigned int g_counter = 0;

__device__ __forceinline__ float seg_term(const float2* __restrict__ p)
{
    const float2 p0 = __ldg(p + 0);
    const float2 p1 = __ldg(p + 1);
    const float2 p2 = __ldg(p + 2);
    const float2 p3 = __ldg(p + 3);

    const float v1x = p1.x - p0.x, v1y = p1.y - p0.y;
    const float v2x = p2.x - p1.x, v2y = p2.y - p1.y;
    const float v3x = p3.x - p2.x, v3y = p3.y - p2.y;

    // direct = (s12 >= 0) depends only on sign of cross(v1,v2):
    // the positive norm product cannot flip the sign.
    const float c12 = v1x * v2y - v1y * v2x;
    const float c13 = v1x * v3y - v1y * v3x;

    const float n2   = (v1x * v1x + v1y * v1y) * (v3x * v3x + v3y * v3y);
    const float sina = c13 * rsqrtf(n2);

    return (c12 >= 0.0f) ? fmaxf(-sina, 0.0f) : fmaxf(sina, 0.0f);
}

__global__ void __launch_bounds__(SEGN) xing_kernel(
    const float* __restrict__ x,
    const uint32_t* __restrict__ scale_raw,
    float* __restrict__ out, int P, int nblocks)
{
    const int t = threadIdx.x;                 // segment index 0..255

    // Base pointer for this block's first row; segment t starts at point 3t.
    const float2* __restrict__ row0 =
        reinterpret_cast<const float2*>(x)
        + (size_t)blockIdx.x * ROWS_PER_BLOCK * N_POINTS + 3 * t;

    float acc = 0.0f;
    #pragma unroll
    for (int r = 0; r < ROWS_PER_BLOCK; r++)
        acc += seg_term(row0 + (size_t)r * N_POINTS);

    // ---- block reduce ----
    #pragma unroll
    for (int o = 16; o > 0; o >>= 1)
        acc += __shfl_down_sync(0xFFFFFFFFu, acc, o);

    __shared__ float s[SEGN / 32];
    __shared__ bool  isLast;
    if ((t & 31) == 0) s[t >> 5] = acc;
    __syncthreads();

    if (t == 0) {
        float bs = 0.0f;
        #pragma unroll
        for (int i = 0; i < SEGN / 32; i++) bs += s[i];
        g_partials[blockIdx.x] = bs;
        __threadfence();
        unsigned int done = atomicAdd(&g_counter, 1u);
        isLast = (done == (unsigned int)(nblocks - 1));
    }
    __syncthreads();

    // ---- last block folds the 2048 partials ----
    if (isLast) {
        float v = 0.0f;
        for (int i = t; i < nblocks; i += SEGN)
            v += __ldcg(&g_partials[i]);

        #pragma unroll
        for (int o = 16; o > 0; o >>= 1)
            v += __shfl_down_sync(0xFFFFFFFFu, v, o);
        if ((t & 31) == 0) s[t >> 5] = v;
        __syncthreads();

        if (t == 0) {
            float total = 0.0f;
            #pragma unroll
            for (int i = 0; i < SEGN / 32; i++) total += s[i];

            // Decode scale: float32 bit pattern vs integer bit pattern.
            uint32_t u  = scale_raw[0];
            float    f  = __uint_as_float(u);
            float    scale;
            if (fabsf(f) >= 1e-30f && fabsf(f) < 1e30f) scale = f;
            else                                        scale = (float)(int)u;

            out[0] = total * scale / ((float)SEGN * (float)P);
            // Reset counter for the next (graph-replayed) launch.
            atomicExch(&g_counter, 0u);
        }
    }
}

extern "C" void kernel_launch(void* const* d_in, const int* in_sizes, int n_in,
                              void* d_out, int out_size)
{
    const float*    x     = (const float*)d_in[0];
    const uint32_t* scale = (const uint32_t*)d_in[1];
    float*          out   = (float*)d_out;

    int P       = in_sizes[0] / (N_POINTS * 2);     // 16384
    int nblocks = P / ROWS_PER_BLOCK;               // 2048

    xing_kernel<<<nblocks, SEGN>>>(x, scale, out, P, nblocks);
}